// round 3
// baseline (speedup 1.0000x reference)
#include <cuda_runtime.h>
#include <cuda_bf16.h>

// Problem-fixed shapes
#define MAXN 50000
#define MAXE 600000
#define D 128
#define ED 16

// ---------------- device scratch (static: no allocs allowed) ----------------
__device__ float g_agg[MAXN * D];     // segment_sum of relu(BN(edge_attr@W1)) rows
__device__ float g_deg[MAXN];         // in-degree (float)
__device__ float g_hnew[MAXN * D];    // h + agg@W2 + deg*b2
__device__ float g_neigh[MAXN * D];   // segment_sum(h_new[src], dst)
__device__ float g_t1[MAXN * D];      // z @ mlp_w1 + b1
__device__ float g_t2[MAXN * D];      // relu(bn(t1)) @ mlp_w2 + b2
__device__ float g_stats[3 * 256];    // 3 x (colsum[128], colsumsq[128])
__device__ float g_scale[3 * 128];    // 3 BN affine folds
__device__ float g_shift[3 * 128];
__device__ int   g_is64;              // edge_index dtype flag

// ---------------- index dtype detection ----------------
// int64 indices in [0, 50000) always have zero high words; packed int32 pairs
// essentially never do (would require every 2nd index == 0).
__global__ void detect_idx(const unsigned long long* __restrict__ ei, int E)
{
    if (threadIdx.x == 0 && blockIdx.x == 0) {
        int n = E < 1024 ? E : 1024;
        int is64 = 1;
        for (int i = 0; i < n; i++)
            if (ei[i] >> 32) { is64 = 0; break; }
        g_is64 = is64;
    }
}

__device__ __forceinline__ int load_idx(const void* ei, long long pos, int is64)
{
    if (is64) return (int)((const long long*)ei)[pos];
    return ((const int*)ei)[pos];
}

// ---------------- edge pass 1: column stats of t = edge_attr@W1 + b1 --------
__global__ void __launch_bounds__(256) edge_pass1(
    const float* __restrict__ attr, const float* __restrict__ w1,
    const float* __restrict__ b1, int E, float* __restrict__ stats)
{
    __shared__ float sa[128 * ED];
    int c = threadIdx.x & 127;
    int half = threadIdx.x >> 7;
    float w[ED];
#pragma unroll
    for (int k = 0; k < ED; k++) w[k] = w1[k * D + c];
    float bc = b1[c];
    float s1 = 0.f, s2 = 0.f;

    for (int base = blockIdx.x * 128; base < E; base += gridDim.x * 128) {
        int ne = min(128, E - base);
        __syncthreads();
        for (int i = threadIdx.x; i < ne * ED; i += 256)
            sa[i] = attr[(long long)base * ED + i];
        __syncthreads();
        for (int e = half; e < ne; e += 2) {
            float t = bc;
#pragma unroll
            for (int k = 0; k < ED; k++) t = fmaf(sa[e * ED + k], w[k], t);
            s1 += t;
            s2 += t * t;
        }
    }
    atomicAdd(&stats[c], s1);
    atomicAdd(&stats[128 + c], s2);
}

// ---------------- finalize BN: scale/shift from stats -----------------------
__global__ void finalize_bn(const float* __restrict__ stats,
                            const float* __restrict__ gamma,
                            const float* __restrict__ beta,
                            float invn, float* __restrict__ scale,
                            float* __restrict__ shift)
{
    int c = threadIdx.x;
    float mean = stats[c] * invn;
    float var = stats[128 + c] * invn - mean * mean;
    float inv = rsqrtf(var + 1e-5f);
    float sc = gamma[c] * inv;
    scale[c] = sc;
    shift[c] = beta[c] - mean * sc;
}

// ---------------- edge pass 2: scatter relu(BN(t)) rows to agg[dst] ---------
__global__ void __launch_bounds__(256) edge_pass2(
    const float* __restrict__ attr, const void* __restrict__ ei,
    const float* __restrict__ w1, const float* __restrict__ b1,
    const float* __restrict__ scale, const float* __restrict__ shift,
    int E, int N, float* __restrict__ agg, float* __restrict__ deg)
{
    __shared__ float sa[64 * ED];
    __shared__ int sd[64];
    int lane = threadIdx.x & 31;
    int grp = threadIdx.x >> 5;  // 8 edge slots per block
    int c4 = lane * 4;
    int is64 = g_is64;

    float4 w[ED];
#pragma unroll
    for (int k = 0; k < ED; k++) w[k] = *(const float4*)&w1[k * D + c4];
    float4 bb = *(const float4*)&b1[c4];
    float4 sc = *(const float4*)&scale[c4];
    float4 sh = *(const float4*)&shift[c4];
    // fold the Linear bias into the BN shift: y = (dot + b1)*sc + sh
    sh.x = fmaf(bb.x, sc.x, sh.x);
    sh.y = fmaf(bb.y, sc.y, sh.y);
    sh.z = fmaf(bb.z, sc.z, sh.z);
    sh.w = fmaf(bb.w, sc.w, sh.w);

    for (int base = blockIdx.x * 64; base < E; base += gridDim.x * 64) {
        int ne = min(64, E - base);
        __syncthreads();
        for (int i = threadIdx.x; i < ne * ED; i += 256)
            sa[i] = attr[(long long)base * ED + i];
        for (int i = threadIdx.x; i < ne; i += 256)
            sd[i] = load_idx(ei, (long long)E + base + i, is64);  // dst row
        __syncthreads();
        for (int e = grp; e < ne; e += 8) {
            int d = sd[e];
            if ((unsigned)d >= (unsigned)N) continue;
            float4 acc = make_float4(0.f, 0.f, 0.f, 0.f);
#pragma unroll
            for (int k = 0; k < ED; k++) {
                float a = sa[e * ED + k];
                acc.x = fmaf(a, w[k].x, acc.x);
                acc.y = fmaf(a, w[k].y, acc.y);
                acc.z = fmaf(a, w[k].z, acc.z);
                acc.w = fmaf(a, w[k].w, acc.w);
            }
            float* p = &agg[(long long)d * D + c4];
            atomicAdd(p + 0, fmaxf(fmaf(acc.x, sc.x, sh.x), 0.f));
            atomicAdd(p + 1, fmaxf(fmaf(acc.y, sc.y, sh.y), 0.f));
            atomicAdd(p + 2, fmaxf(fmaf(acc.z, sc.z, sh.z), 0.f));
            atomicAdd(p + 3, fmaxf(fmaf(acc.w, sc.w, sh.w), 0.f));
            if (lane == 0) atomicAdd(&deg[d], 1.0f);
        }
    }
}

// ---------------- neighbor scatter: neigh[dst] += h_new[src] ----------------
__global__ void __launch_bounds__(256) neigh_scatter(
    const void* __restrict__ ei, const float* __restrict__ hnew,
    float* __restrict__ neigh, int E, int N)
{
    int lane = threadIdx.x & 31;
    int grp = threadIdx.x >> 5;
    int c4 = lane * 4;
    int is64 = g_is64;
    for (int e = blockIdx.x * 8 + grp; e < E; e += gridDim.x * 8) {
        int s = load_idx(ei, e, is64);
        int d = load_idx(ei, (long long)E + e, is64);
        if ((unsigned)s >= (unsigned)N || (unsigned)d >= (unsigned)N) continue;
        float4 v = *(const float4*)&hnew[(long long)s * D + c4];
        float* p = &neigh[(long long)d * D + c4];
        atomicAdd(p + 0, v.x);
        atomicAdd(p + 1, v.y);
        atomicAdd(p + 2, v.z);
        atomicAdd(p + 3, v.w);
    }
}

// ---------------- 128-wide K GEMM with fused pre/post ops -------------------
// MODE 0: out = A@W + hin + deg*bias          (A = agg, W = ee_w2)
// MODE 1: out = (A + A2)@W + bias             (A = hnew, A2 = neigh, W = mlp_w1)
// MODE 2: out = relu(A*scale+shift)@W + bias  (A = t1, W = mlp_w2)
#define GEMM_SMEM ((128 * 132 + 128 * 128) * 4)
template <int MODE>
__global__ void __launch_bounds__(256) gemm128(
    const float* __restrict__ A, const float* __restrict__ A2,
    const float* __restrict__ W, const float* __restrict__ bias,
    const float* __restrict__ scale, const float* __restrict__ shift,
    const float* __restrict__ hin, const float* __restrict__ degv,
    float* __restrict__ out, int N)
{
    extern __shared__ float sm[];
    float* As = sm;              // transposed, padded: As[k*132 + r]
    float* Ws = sm + 128 * 132;  // Ws[k*128 + c]
    int tid = threadIdx.x;
    int row0 = blockIdx.x * 128;

    for (int i = tid; i < 128 * 128; i += 256) Ws[i] = W[i];
    for (int i = tid; i < 128 * 128; i += 256) {
        int r = i >> 7, k = i & 127;
        int row = row0 + r;
        float v = 0.f;
        if (row < N) {
            v = A[(long long)row * D + k];
            if (MODE == 1) v += A2[(long long)row * D + k];
            if (MODE == 2) v = fmaxf(fmaf(v, scale[k], shift[k]), 0.f);
        }
        As[k * 132 + r] = v;
    }
    __syncthreads();

    int tx = tid & 15, ty = tid >> 4;
    float acc[8][8];
#pragma unroll
    for (int i = 0; i < 8; i++)
#pragma unroll
        for (int j = 0; j < 8; j++) acc[i][j] = 0.f;

    for (int k = 0; k < 128; k++) {
        float4 a0 = *(const float4*)&As[k * 132 + ty * 8];
        float4 a1 = *(const float4*)&As[k * 132 + ty * 8 + 4];
        float4 b0 = *(const float4*)&Ws[k * 128 + tx * 8];
        float4 b1 = *(const float4*)&Ws[k * 128 + tx * 8 + 4];
        float a[8] = {a0.x, a0.y, a0.z, a0.w, a1.x, a1.y, a1.z, a1.w};
        float b[8] = {b0.x, b0.y, b0.z, b0.w, b1.x, b1.y, b1.z, b1.w};
#pragma unroll
        for (int i = 0; i < 8; i++)
#pragma unroll
            for (int j = 0; j < 8; j++) acc[i][j] = fmaf(a[i], b[j], acc[i][j]);
    }

    float bs[8];
#pragma unroll
    for (int j = 0; j < 8; j++) bs[j] = bias[tx * 8 + j];

#pragma unroll
    for (int i = 0; i < 8; i++) {
        int row = row0 + ty * 8 + i;
        if (row < N) {
            float o[8];
            if (MODE == 0) {
                float dg = degv[row];
                float4 h0 = *(const float4*)&hin[(long long)row * D + tx * 8];
                float4 h1 = *(const float4*)&hin[(long long)row * D + tx * 8 + 4];
                float hh[8] = {h0.x, h0.y, h0.z, h0.w, h1.x, h1.y, h1.z, h1.w};
#pragma unroll
                for (int j = 0; j < 8; j++) o[j] = acc[i][j] + hh[j] + dg * bs[j];
            } else {
#pragma unroll
                for (int j = 0; j < 8; j++) o[j] = acc[i][j] + bs[j];
            }
            *(float4*)&out[(long long)row * D + tx * 8] = make_float4(o[0], o[1], o[2], o[3]);
            *(float4*)&out[(long long)row * D + tx * 8 + 4] = make_float4(o[4], o[5], o[6], o[7]);
        }
    }
}

// ---------------- column stats over [N,128] ----------------
__global__ void __launch_bounds__(256) colstats(
    const float* __restrict__ X, int N, float* __restrict__ stats)
{
    int c = threadIdx.x & 127;
    int half = threadIdx.x >> 7;
    float s1 = 0.f, s2 = 0.f;
    for (int r = blockIdx.x * 2 + half; r < N; r += gridDim.x * 2) {
        float v = X[(long long)r * D + c];
        s1 += v;
        s2 += v * v;
    }
    atomicAdd(&stats[c], s1);
    atomicAdd(&stats[128 + c], s2);
}

// ---------------- zero scratch buffers ----------------
__global__ void __launch_bounds__(256) zero_scratch(
    float* __restrict__ agg, float* __restrict__ neigh,
    float* __restrict__ deg, float* __restrict__ stats, int N)
{
    int total = N * D;
    for (int i = blockIdx.x * blockDim.x + threadIdx.x; i < total;
         i += gridDim.x * blockDim.x) {
        agg[i] = 0.f;
        neigh[i] = 0.f;
    }
    for (int i = blockIdx.x * blockDim.x + threadIdx.x; i < N;
         i += gridDim.x * blockDim.x)
        deg[i] = 0.f;
    if (blockIdx.x == 0 && threadIdx.x < 256) {
        stats[threadIdx.x] = 0.f;
        stats[256 + threadIdx.x] = 0.f;
        stats[512 + threadIdx.x] = 0.f;
    }
}

// ---------------- final eltwise: out = relu(bn(t2)) ----------------
__global__ void __launch_bounds__(256) bn_relu_out(
    const float* __restrict__ t2, const float* __restrict__ scale,
    const float* __restrict__ shift, float* __restrict__ out, int N)
{
    int total4 = N * 32;  // float4 count
    for (int idx = blockIdx.x * blockDim.x + threadIdx.x; idx < total4;
         idx += gridDim.x * blockDim.x) {
        int c4 = (idx & 31) * 4;
        float4 v = *(const float4*)&t2[(long long)idx * 4];
        float4 sc = *(const float4*)&scale[c4];
        float4 sh = *(const float4*)&shift[c4];
        float4 o;
        o.x = fmaxf(fmaf(v.x, sc.x, sh.x), 0.f);
        o.y = fmaxf(fmaf(v.y, sc.y, sh.y), 0.f);
        o.z = fmaxf(fmaf(v.z, sc.z, sh.z), 0.f);
        o.w = fmaxf(fmaf(v.w, sc.w, sh.w), 0.f);
        *(float4*)&out[(long long)idx * 4] = o;
    }
}

// ---------------- launch ----------------
extern "C" void kernel_launch(void* const* d_in, const int* in_sizes, int n_in,
                              void* d_out, int out_size)
{
    const float* h        = (const float*)d_in[0];
    const void*  ei       = d_in[1];
    const float* attr     = (const float*)d_in[2];
    const float* ee_w1    = (const float*)d_in[3];
    const float* ee_b1    = (const float*)d_in[4];
    const float* ee_g1    = (const float*)d_in[5];
    const float* ee_bb1   = (const float*)d_in[6];
    const float* ee_w2    = (const float*)d_in[7];
    const float* ee_b2    = (const float*)d_in[8];
    const float* mlp_w1   = (const float*)d_in[9];
    const float* mlp_b1   = (const float*)d_in[10];
    const float* mlp_g1   = (const float*)d_in[11];
    const float* mlp_bb1  = (const float*)d_in[12];
    const float* mlp_w2   = (const float*)d_in[13];
    const float* mlp_b2   = (const float*)d_in[14];
    const float* mlp_g2   = (const float*)d_in[15];
    const float* mlp_bb2  = (const float*)d_in[16];

    int N = in_sizes[0] / D;
    int E = in_sizes[1] / 2;
    float* out = (float*)d_out;

    float *p_agg, *p_deg, *p_hnew, *p_neigh, *p_t1, *p_t2, *p_stats, *p_scale, *p_shift;
    cudaGetSymbolAddress((void**)&p_agg, g_agg);
    cudaGetSymbolAddress((void**)&p_deg, g_deg);
    cudaGetSymbolAddress((void**)&p_hnew, g_hnew);
    cudaGetSymbolAddress((void**)&p_neigh, g_neigh);
    cudaGetSymbolAddress((void**)&p_t1, g_t1);
    cudaGetSymbolAddress((void**)&p_t2, g_t2);
    cudaGetSymbolAddress((void**)&p_stats, g_stats);
    cudaGetSymbolAddress((void**)&p_scale, g_scale);
    cudaGetSymbolAddress((void**)&p_shift, g_shift);

    cudaFuncSetAttribute(gemm128<0>, cudaFuncAttributeMaxDynamicSharedMemorySize, GEMM_SMEM);
    cudaFuncSetAttribute(gemm128<1>, cudaFuncAttributeMaxDynamicSharedMemorySize, GEMM_SMEM);
    cudaFuncSetAttribute(gemm128<2>, cudaFuncAttributeMaxDynamicSharedMemorySize, GEMM_SMEM);

    int tiles = (N + 127) / 128;

    // detect edge_index dtype (int32 vs int64) + zero accumulators
    detect_idx<<<1, 32>>>((const unsigned long long*)ei, E);
    zero_scratch<<<592, 256>>>(p_agg, p_neigh, p_deg, p_stats, N);

    // edge encoder: BN stats pass
    edge_pass1<<<1184, 256>>>(attr, ee_w1, ee_b1, E, p_stats);
    finalize_bn<<<1, 128>>>(p_stats, ee_g1, ee_bb1, 1.0f / (float)E, p_scale, p_shift);
    // edge encoder: apply + scatter relu rows (second Linear deferred to node GEMM)
    edge_pass2<<<1184, 256>>>(attr, ei, ee_w1, ee_b1, p_scale, p_shift, E, N, p_agg, p_deg);

    // h_new = h + agg@ee_w2 + deg*ee_b2
    gemm128<0><<<tiles, 256, GEMM_SMEM>>>(p_agg, nullptr, ee_w2, ee_b2,
                                          nullptr, nullptr, h, p_deg, p_hnew, N);

    // neigh = segment_sum(h_new[src], dst)
    neigh_scatter<<<1184, 256>>>(ei, p_hnew, p_neigh, E, N);

    // t1 = (h_new + neigh) @ mlp_w1 + b1
    gemm128<1><<<tiles, 256, GEMM_SMEM>>>(p_hnew, p_neigh, mlp_w1, mlp_b1,
                                          nullptr, nullptr, nullptr, nullptr, p_t1, N);
    colstats<<<592, 256>>>(p_t1, N, p_stats + 256);
    finalize_bn<<<1, 128>>>(p_stats + 256, mlp_g1, mlp_bb1, 1.0f / (float)N,
                            p_scale + 128, p_shift + 128);

    // t2 = relu(bn(t1)) @ mlp_w2 + b2
    gemm128<2><<<tiles, 256, GEMM_SMEM>>>(p_t1, nullptr, mlp_w2, mlp_b2,
                                          p_scale + 128, p_shift + 128,
                                          nullptr, nullptr, p_t2, N);
    colstats<<<592, 256>>>(p_t2, N, p_stats + 512);
    finalize_bn<<<1, 128>>>(p_stats + 512, mlp_g2, mlp_bb2, 1.0f / (float)N,
                            p_scale + 256, p_shift + 256);

    // out = relu(bn(t2))
    int g = min((N * 32 + 255) / 256, 4096);
    bn_relu_out<<<g, 256>>>(p_t2, p_scale + 256, p_shift + 256, out, N);
}

// round 5
// speedup vs baseline: 1.4911x; 1.4911x over previous
#include <cuda_runtime.h>
#include <cuda_bf16.h>

// Problem-fixed shapes
#define MAXN 50000
#define MAXE 600000
#define D 128
#define ED 16

// ---------------- device scratch (static: no allocs allowed) ----------------
__device__ float g_agg[MAXN * D];     // segment_sum of relu(BN(edge_attr@W1)) rows
__device__ float g_deg[MAXN];         // in-degree (float)
__device__ float g_hnew[MAXN * D];    // h + agg@W2 + deg*b2
__device__ float g_neigh[MAXN * D];   // segment_sum(h_new[src], dst)
__device__ float g_t1[MAXN * D];      // z @ mlp_w1 + b1
__device__ float g_t2[MAXN * D];      // relu(bn(t1)) @ mlp_w2 + b2
__device__ float g_stats[3 * 256];    // colstats accumulators
__device__ float g_mom[16 + 256];     // S[16], M[16x16] edge-attr moments
__device__ float g_scale[3 * 128];    // 3 BN affine folds
__device__ float g_shift[3 * 128];
__device__ int   g_is64;              // edge_index dtype flag

// ---------------- index dtype detection ----------------
__global__ void detect_idx(const unsigned long long* __restrict__ ei, int E)
{
    if (threadIdx.x == 0 && blockIdx.x == 0) {
        int n = E < 1024 ? E : 1024;
        int is64 = 1;
        for (int i = 0; i < n; i++)
            if (ei[i] >> 32) { is64 = 0; break; }
        g_is64 = is64;
    }
}

__device__ __forceinline__ int load_idx(const void* ei, long long pos, int is64)
{
    if (is64) return (int)((const long long*)ei)[pos];
    return ((const int*)ei)[pos];
}

// ---------------- edge moments: S = sum attr, M = sum attr attr^T ------------
__global__ void __launch_bounds__(256) edge_moments(
    const float* __restrict__ attr, int E, float* __restrict__ mom)
{
    __shared__ float sa[128 * ED];
    int tid = threadIdx.x;
    int k = tid & 15, l = tid >> 4;
    float m = 0.f, s = 0.f;
    for (int base = blockIdx.x * 128; base < E; base += gridDim.x * 128) {
        int ne = min(128, E - base);
        __syncthreads();
        for (int i = tid; i < ne * ED; i += 256)
            sa[i] = attr[(long long)base * ED + i];
        __syncthreads();
        for (int e = 0; e < ne; e++) {
            float ak = sa[e * ED + k];
            float al = sa[e * ED + l];
            m = fmaf(ak, al, m);
            if (l == 0) s += ak;
        }
    }
    atomicAdd(&mom[16 + l * 16 + k], m);
    if (l == 0) atomicAdd(&mom[k], s);
}

// ---------------- finalize edge BN from moments ------------------------------
__global__ void __launch_bounds__(128) finalize_ee_bn(
    const float* __restrict__ mom, const float* __restrict__ w1,
    const float* __restrict__ b1, const float* __restrict__ gamma,
    const float* __restrict__ beta, float invE,
    float* __restrict__ scale, float* __restrict__ shift)
{
    __shared__ float S[16], M[256];
    int c = threadIdx.x;
    if (c < 16) S[c] = mom[c];
    M[c] = mom[16 + c];
    M[128 + c] = mom[144 + c];
    __syncthreads();

    float wc[16];
#pragma unroll
    for (int k = 0; k < 16; k++) wc[k] = w1[k * D + c];
    float sw = 0.f;
#pragma unroll
    for (int k = 0; k < 16; k++) sw = fmaf(S[k], wc[k], sw);
    float bc = b1[c];
    float mean = sw * invE + bc;
    float q = 0.f;
#pragma unroll
    for (int k = 0; k < 16; k++) {
        float t = 0.f;
#pragma unroll
        for (int l = 0; l < 16; l++) t = fmaf(M[k * 16 + l], wc[l], t);
        q = fmaf(wc[k], t, q);
    }
    float ex2 = q * invE + 2.f * bc * sw * invE + bc * bc;
    float var = ex2 - mean * mean;
    float inv = rsqrtf(var + 1e-5f);
    float sc = gamma[c] * inv;
    scale[c] = sc;
    shift[c] = beta[c] - mean * sc;
}

// ---------------- finalize BN: scale/shift from colstats ---------------------
__global__ void finalize_bn(const float* __restrict__ stats,
                            const float* __restrict__ gamma,
                            const float* __restrict__ beta,
                            float invn, float* __restrict__ scale,
                            float* __restrict__ shift)
{
    int c = threadIdx.x;
    float mean = stats[c] * invn;
    float var = stats[128 + c] * invn - mean * mean;
    float inv = rsqrtf(var + 1e-5f);
    float sc = gamma[c] * inv;
    scale[c] = sc;
    shift[c] = beta[c] - mean * sc;
}

// ---------------- edge pass 2: scatter relu(BN(t)) rows to agg[dst] ---------
__global__ void __launch_bounds__(256) edge_pass2(
    const float* __restrict__ attr, const void* __restrict__ ei,
    const float* __restrict__ w1, const float* __restrict__ b1,
    const float* __restrict__ scale, const float* __restrict__ shift,
    int E, int N, float* __restrict__ agg, float* __restrict__ deg)
{
    __shared__ float sa[64 * ED];
    __shared__ int sd[64];
    int lane = threadIdx.x & 31;
    int grp = threadIdx.x >> 5;  // 8 edge slots per block
    int c4 = lane * 4;
    int is64 = g_is64;

    float4 w[ED];
#pragma unroll
    for (int k = 0; k < ED; k++) w[k] = *(const float4*)&w1[k * D + c4];
    float4 bb = *(const float4*)&b1[c4];
    float4 sc = *(const float4*)&scale[c4];
    float4 sh = *(const float4*)&shift[c4];
    // fold the Linear bias into the BN shift: y = (dot + b1)*sc + sh
    sh.x = fmaf(bb.x, sc.x, sh.x);
    sh.y = fmaf(bb.y, sc.y, sh.y);
    sh.z = fmaf(bb.z, sc.z, sh.z);
    sh.w = fmaf(bb.w, sc.w, sh.w);

    for (int base = blockIdx.x * 64; base < E; base += gridDim.x * 64) {
        int ne = min(64, E - base);
        __syncthreads();
        for (int i = threadIdx.x; i < ne * ED; i += 256)
            sa[i] = attr[(long long)base * ED + i];
        for (int i = threadIdx.x; i < ne; i += 256)
            sd[i] = load_idx(ei, (long long)E + base + i, is64);  // dst row
        __syncthreads();
        for (int e = grp; e < ne; e += 8) {
            int d = sd[e];
            if ((unsigned)d >= (unsigned)N) continue;
            float4 acc = make_float4(0.f, 0.f, 0.f, 0.f);
#pragma unroll
            for (int k = 0; k < ED; k++) {
                float a = sa[e * ED + k];
                acc.x = fmaf(a, w[k].x, acc.x);
                acc.y = fmaf(a, w[k].y, acc.y);
                acc.z = fmaf(a, w[k].z, acc.z);
                acc.w = fmaf(a, w[k].w, acc.w);
            }
            float4 y;
            y.x = fmaxf(fmaf(acc.x, sc.x, sh.x), 0.f);
            y.y = fmaxf(fmaf(acc.y, sc.y, sh.y), 0.f);
            y.z = fmaxf(fmaf(acc.z, sc.z, sh.z), 0.f);
            y.w = fmaxf(fmaf(acc.w, sc.w, sh.w), 0.f);
            atomicAdd((float4*)&agg[(long long)d * D + c4], y);
            if (lane == 0) atomicAdd(&deg[d], 1.0f);
        }
    }
}

// ---------------- neighbor scatter: neigh[dst] += h_new[src] ----------------
__global__ void __launch_bounds__(256) neigh_scatter(
    const void* __restrict__ ei, const float* __restrict__ hnew,
    float* __restrict__ neigh, int E, int N)
{
    int lane = threadIdx.x & 31;
    int grp = threadIdx.x >> 5;
    int c4 = lane * 4;
    int is64 = g_is64;
    for (int e = blockIdx.x * 8 + grp; e < E; e += gridDim.x * 8) {
        int s = load_idx(ei, e, is64);
        int d = load_idx(ei, (long long)E + e, is64);
        if ((unsigned)s >= (unsigned)N || (unsigned)d >= (unsigned)N) continue;
        float4 v = *(const float4*)&hnew[(long long)s * D + c4];
        atomicAdd((float4*)&neigh[(long long)d * D + c4], v);
    }
}

// ---------------- 128-wide K GEMM with fused pre/post ops -------------------
// MODE 0: out = A@W + hin + deg*bias          (A = agg, W = ee_w2)
// MODE 1: out = (A + A2)@W + bias             (A = hnew, A2 = neigh, W = mlp_w1)
// MODE 2: out = relu(A*scale+shift)@W + bias  (A = t1, W = mlp_w2)
#define GEMM_SMEM ((128 * 132 + 128 * 128) * 4)
template <int MODE>
__global__ void __launch_bounds__(256) gemm128(
    const float* __restrict__ A, const float* __restrict__ A2,
    const float* __restrict__ W, const float* __restrict__ bias,
    const float* __restrict__ scale, const float* __restrict__ shift,
    const float* __restrict__ hin, const float* __restrict__ degv,
    float* __restrict__ out, int N)
{
    extern __shared__ float sm[];
    float* As = sm;              // transposed, padded: As[k*132 + r]
    float* Ws = sm + 128 * 132;  // Ws[k*128 + c]
    int tid = threadIdx.x;
    int row0 = blockIdx.x * 128;

    for (int i = tid; i < 128 * 128; i += 256) Ws[i] = W[i];
    for (int i = tid; i < 128 * 128; i += 256) {
        int r = i >> 7, k = i & 127;
        int row = row0 + r;
        float v = 0.f;
        if (row < N) {
            v = A[(long long)row * D + k];
            if (MODE == 1) v += A2[(long long)row * D + k];
            if (MODE == 2) v = fmaxf(fmaf(v, scale[k], shift[k]), 0.f);
        }
        As[k * 132 + r] = v;
    }
    __syncthreads();

    int tx = tid & 15, ty = tid >> 4;
    float acc[8][8];
#pragma unroll
    for (int i = 0; i < 8; i++)
#pragma unroll
        for (int j = 0; j < 8; j++) acc[i][j] = 0.f;

    for (int k = 0; k < 128; k++) {
        float4 a0 = *(const float4*)&As[k * 132 + ty * 8];
        float4 a1 = *(const float4*)&As[k * 132 + ty * 8 + 4];
        float4 b0 = *(const float4*)&Ws[k * 128 + tx * 8];
        float4 b1 = *(const float4*)&Ws[k * 128 + tx * 8 + 4];
        float a[8] = {a0.x, a0.y, a0.z, a0.w, a1.x, a1.y, a1.z, a1.w};
        float b[8] = {b0.x, b0.y, b0.z, b0.w, b1.x, b1.y, b1.z, b1.w};
#pragma unroll
        for (int i = 0; i < 8; i++)
#pragma unroll
            for (int j = 0; j < 8; j++) acc[i][j] = fmaf(a[i], b[j], acc[i][j]);
    }

    float bs[8];
#pragma unroll
    for (int j = 0; j < 8; j++) bs[j] = bias[tx * 8 + j];

#pragma unroll
    for (int i = 0; i < 8; i++) {
        int row = row0 + ty * 8 + i;
        if (row < N) {
            float o[8];
            if (MODE == 0) {
                float dg = degv[row];
                float4 h0 = *(const float4*)&hin[(long long)row * D + tx * 8];
                float4 h1 = *(const float4*)&hin[(long long)row * D + tx * 8 + 4];
                float hh[8] = {h0.x, h0.y, h0.z, h0.w, h1.x, h1.y, h1.z, h1.w};
#pragma unroll
                for (int j = 0; j < 8; j++) o[j] = acc[i][j] + hh[j] + dg * bs[j];
            } else {
#pragma unroll
                for (int j = 0; j < 8; j++) o[j] = acc[i][j] + bs[j];
            }
            *(float4*)&out[(long long)row * D + tx * 8] = make_float4(o[0], o[1], o[2], o[3]);
            *(float4*)&out[(long long)row * D + tx * 8 + 4] = make_float4(o[4], o[5], o[6], o[7]);
        }
    }
}

// ---------------- column stats over [N,128] ----------------
__global__ void __launch_bounds__(256) colstats(
    const float* __restrict__ X, int N, float* __restrict__ stats)
{
    int c = threadIdx.x & 127;
    int half = threadIdx.x >> 7;
    float s1 = 0.f, s2 = 0.f;
    for (int r = blockIdx.x * 2 + half; r < N; r += gridDim.x * 2) {
        float v = X[(long long)r * D + c];
        s1 += v;
        s2 += v * v;
    }
    atomicAdd(&stats[c], s1);
    atomicAdd(&stats[128 + c], s2);
}

// ---------------- zero scratch buffers ----------------
__global__ void __launch_bounds__(256) zero_scratch(
    float* __restrict__ agg, float* __restrict__ neigh,
    float* __restrict__ deg, float* __restrict__ stats,
    float* __restrict__ mom, int N)
{
    int gtid = blockIdx.x * blockDim.x + threadIdx.x;
    int total = N * D;
    for (int i = gtid; i < total; i += gridDim.x * blockDim.x) {
        agg[i] = 0.f;
        neigh[i] = 0.f;
    }
    for (int i = gtid; i < N; i += gridDim.x * blockDim.x)
        deg[i] = 0.f;
    // small accumulators: zero ALL of stats[768] and mom[272]
    if (gtid < 768) stats[gtid] = 0.f;
    if (gtid < 272) mom[gtid] = 0.f;
}

// ---------------- final eltwise: out = relu(bn(t2)) ----------------
__global__ void __launch_bounds__(256) bn_relu_out(
    const float* __restrict__ t2, const float* __restrict__ scale,
    const float* __restrict__ shift, float* __restrict__ out, int N)
{
    int total4 = N * 32;  // float4 count
    for (int idx = blockIdx.x * blockDim.x + threadIdx.x; idx < total4;
         idx += gridDim.x * blockDim.x) {
        int c4 = (idx & 31) * 4;
        float4 v = *(const float4*)&t2[(long long)idx * 4];
        float4 sc = *(const float4*)&scale[c4];
        float4 sh = *(const float4*)&shift[c4];
        float4 o;
        o.x = fmaxf(fmaf(v.x, sc.x, sh.x), 0.f);
        o.y = fmaxf(fmaf(v.y, sc.y, sh.y), 0.f);
        o.z = fmaxf(fmaf(v.z, sc.z, sh.z), 0.f);
        o.w = fmaxf(fmaf(v.w, sc.w, sh.w), 0.f);
        *(float4*)&out[(long long)idx * 4] = o;
    }
}

// ---------------- launch ----------------
extern "C" void kernel_launch(void* const* d_in, const int* in_sizes, int n_in,
                              void* d_out, int out_size)
{
    const float* h        = (const float*)d_in[0];
    const void*  ei       = d_in[1];
    const float* attr     = (const float*)d_in[2];
    const float* ee_w1    = (const float*)d_in[3];
    const float* ee_b1    = (const float*)d_in[4];
    const float* ee_g1    = (const float*)d_in[5];
    const float* ee_bb1   = (const float*)d_in[6];
    const float* ee_w2    = (const float*)d_in[7];
    const float* ee_b2    = (const float*)d_in[8];
    const float* mlp_w1   = (const float*)d_in[9];
    const float* mlp_b1   = (const float*)d_in[10];
    const float* mlp_g1   = (const float*)d_in[11];
    const float* mlp_bb1  = (const float*)d_in[12];
    const float* mlp_w2   = (const float*)d_in[13];
    const float* mlp_b2   = (const float*)d_in[14];
    const float* mlp_g2   = (const float*)d_in[15];
    const float* mlp_bb2  = (const float*)d_in[16];

    int N = in_sizes[0] / D;
    int E = in_sizes[1] / 2;
    float* out = (float*)d_out;

    float *p_agg, *p_deg, *p_hnew, *p_neigh, *p_t1, *p_t2, *p_stats, *p_mom, *p_scale, *p_shift;
    cudaGetSymbolAddress((void**)&p_agg, g_agg);
    cudaGetSymbolAddress((void**)&p_deg, g_deg);
    cudaGetSymbolAddress((void**)&p_hnew, g_hnew);
    cudaGetSymbolAddress((void**)&p_neigh, g_neigh);
    cudaGetSymbolAddress((void**)&p_t1, g_t1);
    cudaGetSymbolAddress((void**)&p_t2, g_t2);
    cudaGetSymbolAddress((void**)&p_stats, g_stats);
    cudaGetSymbolAddress((void**)&p_mom, g_mom);
    cudaGetSymbolAddress((void**)&p_scale, g_scale);
    cudaGetSymbolAddress((void**)&p_shift, g_shift);

    cudaFuncSetAttribute(gemm128<0>, cudaFuncAttributeMaxDynamicSharedMemorySize, GEMM_SMEM);
    cudaFuncSetAttribute(gemm128<1>, cudaFuncAttributeMaxDynamicSharedMemorySize, GEMM_SMEM);
    cudaFuncSetAttribute(gemm128<2>, cudaFuncAttributeMaxDynamicSharedMemorySize, GEMM_SMEM);

    int tiles = (N + 127) / 128;

    // detect edge_index dtype (int32 vs int64) + zero accumulators
    detect_idx<<<1, 32>>>((const unsigned long long*)ei, E);
    zero_scratch<<<592, 256>>>(p_agg, p_neigh, p_deg, p_stats, p_mom, N);

    // edge encoder BN stats via closed-form moments (affine map of attr moments)
    edge_moments<<<1184, 256>>>(attr, E, p_mom);
    finalize_ee_bn<<<1, 128>>>(p_mom, ee_w1, ee_b1, ee_g1, ee_bb1,
                               1.0f / (float)E, p_scale, p_shift);

    // edge encoder: apply + scatter relu rows (second Linear deferred to node GEMM)
    edge_pass2<<<1184, 256>>>(attr, ei, ee_w1, ee_b1, p_scale, p_shift, E, N, p_agg, p_deg);

    // h_new = h + agg@ee_w2 + deg*ee_b2
    gemm128<0><<<tiles, 256, GEMM_SMEM>>>(p_agg, nullptr, ee_w2, ee_b2,
                                          nullptr, nullptr, h, p_deg, p_hnew, N);

    // neigh = segment_sum(h_new[src], dst)
    neigh_scatter<<<1184, 256>>>(ei, p_hnew, p_neigh, E, N);

    // t1 = (h_new + neigh) @ mlp_w1 + b1
    gemm128<1><<<tiles, 256, GEMM_SMEM>>>(p_hnew, p_neigh, mlp_w1, mlp_b1,
                                          nullptr, nullptr, nullptr, nullptr, p_t1, N);
    colstats<<<592, 256>>>(p_t1, N, p_stats + 256);
    finalize_bn<<<1, 128>>>(p_stats + 256, mlp_g1, mlp_bb1, 1.0f / (float)N,
                            p_scale + 128, p_shift + 128);

    // t2 = relu(bn(t1)) @ mlp_w2 + b2
    gemm128<2><<<tiles, 256, GEMM_SMEM>>>(p_t1, nullptr, mlp_w2, mlp_b2,
                                          p_scale + 128, p_shift + 128,
                                          nullptr, nullptr, p_t2, N);
    colstats<<<592, 256>>>(p_t2, N, p_stats + 512);
    finalize_bn<<<1, 128>>>(p_stats + 512, mlp_g2, mlp_bb2, 1.0f / (float)N,
                            p_scale + 256, p_shift + 256);

    // out = relu(bn(t2))
    int g = min((N * 32 + 255) / 256, 4096);
    bn_relu_out<<<g, 256>>>(p_t2, p_scale + 256, p_shift + 256, out, N);
}